// round 2
// baseline (speedup 1.0000x reference)
#include <cuda_runtime.h>

#define TT 128
#define CK 16
#define DMAX 16
#define NTHREADS 256

__device__ __forceinline__ float eluf(float v) {
    return v > 0.f ? v : expm1f(v);
}

__device__ __forceinline__ void ffma2(unsigned long long &d,
                                      unsigned long long a,
                                      unsigned long long b) {
    asm("fma.rn.f32x2 %0, %1, %2, %0;" : "+l"(d) : "l"(a), "l"(b));
}

__device__ __forceinline__ unsigned long long pack2(float lo, float hi) {
    unsigned long long r;
    asm("mov.b64 %0, {%1, %2};" : "=l"(r) : "f"(lo), "f"(hi));
    return r;
}

__device__ __forceinline__ void unpack2(unsigned long long v, float &lo, float &hi) {
    asm("mov.b64 {%0, %1}, %2;" : "=f"(lo), "=f"(hi) : "l"(v));
}

// Causal dilated conv (K=2) / 1x1 conv, CO=128 fixed, fused epilogues.
// MODE 0: out = elu(conv + bias)
// MODE 1: out = elu(elu(conv + bias) + res)
// MODE 2: out = elu(elu(conv + bias) + res) + skip
// MODE 3: out = conv + bias            (1x1 downsample, KSIZE=1, D=0)
template<int CIN, int KSIZE, int MODE, int D>
__global__ void __launch_bounds__(NTHREADS, 2)
conv_tb_kernel(const float* __restrict__ x,     // [B, CIN, S]
               const float* __restrict__ w,     // [CO, CIN, KSIZE]
               const float* __restrict__ bias,  // [CO]
               const float* __restrict__ res,   // [B, CO, S] or null
               const float* __restrict__ skip,  // [B, CO, S] or null
               float* __restrict__ out)         // [B, CO, S]
{
    constexpr int S  = 4096;
    constexpr int CO = 128;
    constexpr int W  = TT + D;

    __shared__ __align__(16) float sx[CK][TT + DMAX];
    __shared__ __align__(16) float sw0[CK][2 * CO];
    __shared__ __align__(16) float sw1[CK][2 * CO];

    const int tid = threadIdx.x;
    const int tt  = tid & 15;   // time group:   t = t0 + 2*tt + 32*q + h
    const int tco = tid >> 4;   // co group:     co = tco + 16*c
    const int t0  = blockIdx.x * TT;
    const int b   = blockIdx.y;

    const float* xb = x + (size_t)b * CIN * S;

    unsigned long long acc[8][4];
    #pragma unroll
    for (int c = 0; c < 8; ++c)
        #pragma unroll
        for (int q = 0; q < 4; ++q) acc[c][q] = 0ull;

    for (int cc = 0; cc < CIN; cc += CK) {
        __syncthreads();
        // stage x chunk [CK][TT+D], left zero-pad at t<0
        for (int i = tid; i < CK * W; i += NTHREADS) {
            int ci = i / W;
            int j  = i - ci * W;
            int t  = t0 - D + j;
            sx[ci][j] = (t >= 0) ? xb[(size_t)(cc + ci) * S + t] : 0.f;
        }
        // stage weight chunk, each value duplicated into an f32x2 pair
        for (int i = tid; i < CK * CO; i += NTHREADS) {
            int ci = i >> 7;
            int co = i & (CO - 1);
            const float* wp = w + ((size_t)co * CIN + cc + ci) * KSIZE;
            if (KSIZE == 2) {
                float v0 = wp[0];
                float v1 = wp[1];
                *(float2*)&sw0[ci][co * 2] = make_float2(v0, v0);
                *(float2*)&sw1[ci][co * 2] = make_float2(v1, v1);
            } else {
                float v1 = wp[0];
                *(float2*)&sw1[ci][co * 2] = make_float2(v1, v1);
            }
        }
        __syncthreads();

        #pragma unroll 2
        for (int ci = 0; ci < CK; ++ci) {
            const float* sxp = &sx[ci][2 * tt];
            unsigned long long xd[4], xt[4];
            #pragma unroll
            for (int q = 0; q < 4; ++q) {
                if (KSIZE == 2)
                    xd[q] = *(const unsigned long long*)(sxp + 32 * q);       // x[t-D]
                if ((D & 1) == 0)
                    xt[q] = *(const unsigned long long*)(sxp + 32 * q + D);   // x[t]
                else
                    xt[q] = pack2(sxp[32 * q + D], sxp[32 * q + D + 1]);
            }
            #pragma unroll
            for (int c = 0; c < 8; ++c) {
                int co2 = (tco + 16 * c) * 2;
                unsigned long long w1v = *(const unsigned long long*)&sw1[ci][co2];
                if (KSIZE == 2) {
                    unsigned long long w0v = *(const unsigned long long*)&sw0[ci][co2];
                    #pragma unroll
                    for (int q = 0; q < 4; ++q) ffma2(acc[c][q], w0v, xd[q]);
                }
                #pragma unroll
                for (int q = 0; q < 4; ++q) ffma2(acc[c][q], w1v, xt[q]);
            }
        }
    }

    // fused epilogue
    #pragma unroll
    for (int c = 0; c < 8; ++c) {
        int co = tco + 16 * c;
        float bv = bias[co];
        size_t ob = ((size_t)b * CO + co) * S + t0 + 2 * tt;
        #pragma unroll
        for (int q = 0; q < 4; ++q) {
            float lo, hi;
            unpack2(acc[c][q], lo, hi);
            lo += bv; hi += bv;
            size_t o = ob + 32 * q;
            if (MODE == 0) {
                lo = eluf(lo); hi = eluf(hi);
            } else if (MODE == 1 || MODE == 2) {
                float2 r = *(const float2*)(res + o);
                lo = eluf(eluf(lo) + r.x);
                hi = eluf(eluf(hi) + r.y);
                if (MODE == 2) {
                    float2 s = *(const float2*)(skip + o);
                    lo += s.x; hi += s.y;
                }
            }
            // MODE 3: raw conv + bias
            *(float2*)(out + o) = make_float2(lo, hi);
        }
    }
}

// Scratch (device globals; no allocation in kernel_launch)
#define TENSOR_ELEMS ((size_t)16 * 128 * 4096)
__device__ float g_bufA[TENSOR_ELEMS];
__device__ float g_bufB[TENSOR_ELEMS];
__device__ float g_bufC[TENSOR_ELEMS];
__device__ float g_bufT[TENSOR_ELEMS];

extern "C" void kernel_launch(void* const* d_in, const int* in_sizes, int n_in,
                              void* d_out, int out_size) {
    const float* x    = (const float*)d_in[0];
    const float* w1_0 = (const float*)d_in[1];
    const float* b1_0 = (const float*)d_in[2];
    const float* w2_0 = (const float*)d_in[3];
    const float* b2_0 = (const float*)d_in[4];
    const float* ds_w = (const float*)d_in[5];
    const float* ds_b = (const float*)d_in[6];
    const float* W1   = (const float*)d_in[7];  // [4,128,128,2]
    const float* B1   = (const float*)d_in[8];  // [4,128]
    const float* W2   = (const float*)d_in[9];  // [4,128,128,2]
    const float* B2   = (const float*)d_in[10]; // [4,128]
    float* out = (float*)d_out;

    float *A, *Bf, *C, *T;
    cudaGetSymbolAddress((void**)&A,  g_bufA);
    cudaGetSymbolAddress((void**)&Bf, g_bufB);
    cudaGetSymbolAddress((void**)&C,  g_bufC);
    cudaGetSymbolAddress((void**)&T,  g_bufT);

    dim3 grid(4096 / TT, 16);
    const size_t LW = (size_t)128 * 128 * 2;  // per-layer weight stride

    // layer 0 (dilation 1, Cin=64, downsample residual)
    conv_tb_kernel<64, 1, 3, 0><<<grid, NTHREADS>>>(x, ds_w, ds_b, nullptr, nullptr, C);   // C = ds(x)
    conv_tb_kernel<64, 2, 0, 1><<<grid, NTHREADS>>>(x, w1_0, b1_0, nullptr, nullptr, T);
    conv_tb_kernel<128, 2, 1, 1><<<grid, NTHREADS>>>(T, w2_0, b2_0, C, nullptr, A);        // A = x1

    // layer 1 (dilation 2)
    conv_tb_kernel<128, 2, 0, 2><<<grid, NTHREADS>>>(A, W1 + 0 * LW, B1 + 0,   nullptr, nullptr, T);
    conv_tb_kernel<128, 2, 1, 2><<<grid, NTHREADS>>>(T, W2 + 0 * LW, B2 + 0,   A, nullptr, Bf);  // Bf = x2

    // layer 2 (dilation 4)
    conv_tb_kernel<128, 2, 0, 4><<<grid, NTHREADS>>>(Bf, W1 + 1 * LW, B1 + 128, nullptr, nullptr, T);
    conv_tb_kernel<128, 2, 1, 4><<<grid, NTHREADS>>>(T,  W2 + 1 * LW, B2 + 128, Bf, nullptr, C); // C = x3

    // layer 3 (dilation 8)
    conv_tb_kernel<128, 2, 0, 8><<<grid, NTHREADS>>>(C, W1 + 2 * LW, B1 + 256, nullptr, nullptr, T);
    conv_tb_kernel<128, 2, 1, 8><<<grid, NTHREADS>>>(T, W2 + 2 * LW, B2 + 256, C, nullptr, Bf);  // Bf = x4

    // layer 4 (dilation 16) + final skip add of x1 (A)
    conv_tb_kernel<128, 2, 0, 16><<<grid, NTHREADS>>>(Bf, W1 + 3 * LW, B1 + 384, nullptr, nullptr, T);
    conv_tb_kernel<128, 2, 2, 16><<<grid, NTHREADS>>>(T,  W2 + 3 * LW, B2 + 384, Bf, A, out);
}

// round 3
// speedup vs baseline: 1.2258x; 1.2258x over previous
#include <cuda_runtime.h>

#define TT 128
#define CK 16
#define DMAX 16
#define NTHREADS 256
#define CO 128

__device__ __forceinline__ float eluf(float v) {
    return v > 0.f ? v : expm1f(v);
}

__device__ __forceinline__ void ffma2(unsigned long long &d,
                                      unsigned long long a,
                                      unsigned long long b) {
    asm("fma.rn.f32x2 %0, %1, %2, %0;" : "+l"(d) : "l"(a), "l"(b));
}

__device__ __forceinline__ unsigned long long pack2(float lo, float hi) {
    unsigned long long r;
    asm("mov.b64 %0, {%1, %2};" : "=l"(r) : "f"(lo), "f"(hi));
    return r;
}

__device__ __forceinline__ void unpack2(unsigned long long v, float &lo, float &hi) {
    asm("mov.b64 {%0, %1}, %2;" : "=f"(lo), "=f"(hi) : "l"(v));
}

// Transpose weights [CO][CIN][K] -> [CIN*K][CO] (k-major rows, coalesced writes)
__global__ void transpose_w_kernel(const float* __restrict__ src,
                                   float* __restrict__ dst, int CIN, int K) {
    int n = CIN * K * CO;
    for (int id = blockIdx.x * blockDim.x + threadIdx.x; id < n;
         id += gridDim.x * blockDim.x) {
        int co = id & (CO - 1);
        int r  = id >> 7;
        int ci = r / K;
        int tap = r - ci * K;
        dst[id] = src[(co * CIN + ci) * K + tap];
    }
}

// Causal dilated conv (K=2) / 1x1 conv, CO=128, fused epilogues, double-buffered.
// MODE 0: out = elu(conv + bias)
// MODE 1: out = elu(elu(conv + bias) + res)
// MODE 2: out = elu(elu(conv + bias) + res) + skip
// MODE 3: out = conv + bias            (1x1 downsample, KSIZE=1, D=0)
template<int CIN, int KSIZE, int MODE, int D>
__global__ void __launch_bounds__(NTHREADS, 2)
conv_tb_kernel(const float* __restrict__ x,     // [B, CIN, S]
               const float* __restrict__ wT,    // [CIN*KSIZE, CO] pre-transposed
               const float* __restrict__ bias,  // [CO]
               const float* __restrict__ res,   // [B, CO, S] or null
               const float* __restrict__ skip,  // [B, CO, S] or null
               float* __restrict__ out)         // [B, CO, S]
{
    constexpr int S   = 4096;
    constexpr int W   = TT + D;
    constexpr int XR  = TT + DMAX;        // x row stride in smem
    constexpr int XSZ = CK * XR;          // per-buffer x floats
    constexpr int WSZ = CK * KSIZE * CO;  // per-buffer w floats
    constexpr int NCH = CIN / CK;

    extern __shared__ __align__(16) float smem[];
    float* sxb[2] = { smem, smem + XSZ };
    float* swb[2] = { smem + 2 * XSZ, smem + 2 * XSZ + WSZ };

    const int tid = threadIdx.x;
    const int tt  = tid & 15;   // time group:  t = t0 + 2*tt + 32*q + h
    const int tco = tid >> 4;   // co group:    co = tco + 16*c
    const int t0  = blockIdx.x * TT;
    const int b   = blockIdx.y;

    const float* xb = x + (size_t)b * CIN * S;

    unsigned long long acc[8][4];
    #pragma unroll
    for (int c = 0; c < 8; ++c)
        #pragma unroll
        for (int q = 0; q < 4; ++q) acc[c][q] = 0ull;

    // ---- staging helper ----
    auto stage = [&](int k, int s) {
        int cc = k * CK;
        float* dx = sxb[s];
        #pragma unroll 2
        for (int i = tid; i < CK * W; i += NTHREADS) {
            int ci = i / W;
            int j  = i - ci * W;
            int t  = t0 - D + j;
            dx[ci * XR + j] = (t >= 0) ? xb[(size_t)(cc + ci) * S + t] : 0.f;
        }
        const float4* wsrc = (const float4*)(wT + (size_t)cc * KSIZE * CO);
        float4* wdst = (float4*)swb[s];
        #pragma unroll
        for (int i = tid; i < WSZ / 4; i += NTHREADS)
            wdst[i] = wsrc[i];
    };

    stage(0, 0);
    __syncthreads();

    for (int k = 0; k < NCH; ++k) {
        int s = k & 1;
        if (k + 1 < NCH) stage(k + 1, s ^ 1);

        const float* sx = sxb[s];
        const float* sw = swb[s];

        #pragma unroll 2
        for (int ci = 0; ci < CK; ++ci) {
            const float* sxp = sx + ci * XR + 2 * tt;
            unsigned long long xd[4], xt[4];
            #pragma unroll
            for (int q = 0; q < 4; ++q) {
                if (KSIZE == 2)
                    xd[q] = *(const unsigned long long*)(sxp + 32 * q);       // x[t-D]
                if ((D & 1) == 0)
                    xt[q] = *(const unsigned long long*)(sxp + 32 * q + D);   // x[t]
                else
                    xt[q] = pack2(sxp[32 * q + D], sxp[32 * q + D + 1]);
            }
            #pragma unroll
            for (int c = 0; c < 8; ++c) {
                int co = tco + 16 * c;
                if (KSIZE == 2) {
                    float w0s = sw[(2 * ci) * CO + co];
                    float w1s = sw[(2 * ci + 1) * CO + co];
                    unsigned long long w0v = pack2(w0s, w0s);
                    unsigned long long w1v = pack2(w1s, w1s);
                    #pragma unroll
                    for (int q = 0; q < 4; ++q) ffma2(acc[c][q], w0v, xd[q]);
                    #pragma unroll
                    for (int q = 0; q < 4; ++q) ffma2(acc[c][q], w1v, xt[q]);
                } else {
                    float w1s = sw[ci * CO + co];
                    unsigned long long w1v = pack2(w1s, w1s);
                    #pragma unroll
                    for (int q = 0; q < 4; ++q) ffma2(acc[c][q], w1v, xt[q]);
                }
            }
        }
        __syncthreads();
    }

    // fused epilogue
    #pragma unroll
    for (int c = 0; c < 8; ++c) {
        int co = tco + 16 * c;
        float bv = __ldg(bias + co);
        size_t ob = ((size_t)b * CO + co) * S + t0 + 2 * tt;
        #pragma unroll
        for (int q = 0; q < 4; ++q) {
            float lo, hi;
            unpack2(acc[c][q], lo, hi);
            lo += bv; hi += bv;
            size_t o = ob + 32 * q;
            if (MODE == 0) {
                lo = eluf(lo); hi = eluf(hi);
            } else if (MODE == 1 || MODE == 2) {
                float2 r = *(const float2*)(res + o);
                lo = eluf(eluf(lo) + r.x);
                hi = eluf(eluf(hi) + r.y);
                if (MODE == 2) {
                    float2 s2 = *(const float2*)(skip + o);
                    lo += s2.x; hi += s2.y;
                }
            }
            // MODE 3: raw conv + bias
            *(float2*)(out + o) = make_float2(lo, hi);
        }
    }
}

// Scratch (device globals; no allocation in kernel_launch)
#define TENSOR_ELEMS ((size_t)16 * 128 * 4096)
__device__ float g_bufA[TENSOR_ELEMS];
__device__ float g_bufB[TENSOR_ELEMS];
__device__ float g_bufC[TENSOR_ELEMS];
__device__ float g_bufT[TENSOR_ELEMS];
__device__ float g_wT[360448];  // all transposed weights

// wT float offsets
#define OFF_DS   0        // 64 rows  * 128
#define OFF_W10  8192     // 128 rows * 128
#define OFF_W20  24576    // 256 rows * 128
#define OFF_L(i) (57344 + (size_t)(i) * 65536)        // W1[i]: 256 rows
#define OFF_L2(i) (57344 + (size_t)(i) * 65536 + 32768)  // W2[i]: 256 rows

extern "C" void kernel_launch(void* const* d_in, const int* in_sizes, int n_in,
                              void* d_out, int out_size) {
    const float* x    = (const float*)d_in[0];
    const float* w1_0 = (const float*)d_in[1];
    const float* b1_0 = (const float*)d_in[2];
    const float* w2_0 = (const float*)d_in[3];
    const float* b2_0 = (const float*)d_in[4];
    const float* ds_w = (const float*)d_in[5];
    const float* ds_b = (const float*)d_in[6];
    const float* W1   = (const float*)d_in[7];  // [4,128,128,2]
    const float* B1   = (const float*)d_in[8];  // [4,128]
    const float* W2   = (const float*)d_in[9];  // [4,128,128,2]
    const float* B2   = (const float*)d_in[10]; // [4,128]
    float* out = (float*)d_out;

    float *A, *Bf, *C, *T, *WTp;
    cudaGetSymbolAddress((void**)&A,   g_bufA);
    cudaGetSymbolAddress((void**)&Bf,  g_bufB);
    cudaGetSymbolAddress((void**)&C,   g_bufC);
    cudaGetSymbolAddress((void**)&T,   g_bufT);
    cudaGetSymbolAddress((void**)&WTp, g_wT);

    // ---- weight transposes (cheap prep) ----
    transpose_w_kernel<<<16, 256>>>(ds_w, WTp + OFF_DS, 64, 1);
    transpose_w_kernel<<<64, 256>>>(w1_0, WTp + OFF_W10, 64, 2);
    transpose_w_kernel<<<128, 256>>>(w2_0, WTp + OFF_W20, 128, 2);
    const size_t LW = (size_t)128 * 128 * 2;
    for (int i = 0; i < 4; ++i) {
        transpose_w_kernel<<<128, 256>>>(W1 + i * LW, WTp + OFF_L(i), 128, 2);
        transpose_w_kernel<<<128, 256>>>(W2 + i * LW, WTp + OFF_L2(i), 128, 2);
    }

    dim3 grid(4096 / TT, 16);

    // dynamic smem sizes
    const int smemK2 = (2 * CK * (TT + DMAX) + 2 * CK * 2 * CO) * 4;  // 51200
    const int smemK1 = (2 * CK * (TT + DMAX) + 2 * CK * 1 * CO) * 4;  // 34816

    cudaFuncSetAttribute(conv_tb_kernel<64, 1, 3, 0>,  cudaFuncAttributeMaxDynamicSharedMemorySize, smemK1);
    cudaFuncSetAttribute(conv_tb_kernel<64, 2, 0, 1>,  cudaFuncAttributeMaxDynamicSharedMemorySize, smemK2);
    cudaFuncSetAttribute(conv_tb_kernel<128, 2, 1, 1>, cudaFuncAttributeMaxDynamicSharedMemorySize, smemK2);
    cudaFuncSetAttribute(conv_tb_kernel<128, 2, 0, 2>, cudaFuncAttributeMaxDynamicSharedMemorySize, smemK2);
    cudaFuncSetAttribute(conv_tb_kernel<128, 2, 1, 2>, cudaFuncAttributeMaxDynamicSharedMemorySize, smemK2);
    cudaFuncSetAttribute(conv_tb_kernel<128, 2, 0, 4>, cudaFuncAttributeMaxDynamicSharedMemorySize, smemK2);
    cudaFuncSetAttribute(conv_tb_kernel<128, 2, 1, 4>, cudaFuncAttributeMaxDynamicSharedMemorySize, smemK2);
    cudaFuncSetAttribute(conv_tb_kernel<128, 2, 0, 8>, cudaFuncAttributeMaxDynamicSharedMemorySize, smemK2);
    cudaFuncSetAttribute(conv_tb_kernel<128, 2, 1, 8>, cudaFuncAttributeMaxDynamicSharedMemorySize, smemK2);
    cudaFuncSetAttribute(conv_tb_kernel<128, 2, 0, 16>, cudaFuncAttributeMaxDynamicSharedMemorySize, smemK2);
    cudaFuncSetAttribute(conv_tb_kernel<128, 2, 2, 16>, cudaFuncAttributeMaxDynamicSharedMemorySize, smemK2);

    // layer 0 (dilation 1, Cin=64, downsample residual)
    conv_tb_kernel<64, 1, 3, 0><<<grid, NTHREADS, smemK1>>>(x, WTp + OFF_DS, ds_b, nullptr, nullptr, C);  // C = ds(x)
    conv_tb_kernel<64, 2, 0, 1><<<grid, NTHREADS, smemK2>>>(x, WTp + OFF_W10, b1_0, nullptr, nullptr, T);
    conv_tb_kernel<128, 2, 1, 1><<<grid, NTHREADS, smemK2>>>(T, WTp + OFF_W20, b2_0, C, nullptr, A);      // A = x1

    // layer 1 (dilation 2)
    conv_tb_kernel<128, 2, 0, 2><<<grid, NTHREADS, smemK2>>>(A, WTp + OFF_L(0), B1 + 0,   nullptr, nullptr, T);
    conv_tb_kernel<128, 2, 1, 2><<<grid, NTHREADS, smemK2>>>(T, WTp + OFF_L2(0), B2 + 0,  A, nullptr, Bf); // Bf = x2

    // layer 2 (dilation 4)
    conv_tb_kernel<128, 2, 0, 4><<<grid, NTHREADS, smemK2>>>(Bf, WTp + OFF_L(1), B1 + 128, nullptr, nullptr, T);
    conv_tb_kernel<128, 2, 1, 4><<<grid, NTHREADS, smemK2>>>(T,  WTp + OFF_L2(1), B2 + 128, Bf, nullptr, C); // C = x3

    // layer 3 (dilation 8)
    conv_tb_kernel<128, 2, 0, 8><<<grid, NTHREADS, smemK2>>>(C, WTp + OFF_L(2), B1 + 256, nullptr, nullptr, T);
    conv_tb_kernel<128, 2, 1, 8><<<grid, NTHREADS, smemK2>>>(T, WTp + OFF_L2(2), B2 + 256, C, nullptr, Bf);  // Bf = x4

    // layer 4 (dilation 16) + final skip add of x1 (A)
    conv_tb_kernel<128, 2, 0, 16><<<grid, NTHREADS, smemK2>>>(Bf, WTp + OFF_L(3), B1 + 384, nullptr, nullptr, T);
    conv_tb_kernel<128, 2, 2, 16><<<grid, NTHREADS, smemK2>>>(T,  WTp + OFF_L2(3), B2 + 384, Bf, A, out);
}

// round 6
// speedup vs baseline: 1.2774x; 1.0420x over previous
#include <cuda_runtime.h>
#include <cstdint>

#define TT 128
#define CK 16
#define DMAX 16
#define NTHREADS 256
#define CO 128

__device__ __forceinline__ float eluf(float v) {
    return v > 0.f ? v : expm1f(v);
}

__device__ __forceinline__ void ffma2(unsigned long long &d,
                                      unsigned long long a,
                                      unsigned long long b) {
    asm("fma.rn.f32x2 %0, %1, %2, %0;" : "+l"(d) : "l"(a), "l"(b));
}

__device__ __forceinline__ unsigned long long pack2(float lo, float hi) {
    unsigned long long r;
    asm("mov.b64 %0, {%1, %2};" : "=l"(r) : "f"(lo), "f"(hi));
    return r;
}

__device__ __forceinline__ void unpack2(unsigned long long v, float &lo, float &hi) {
    asm("mov.b64 {%0, %1}, %2;" : "=f"(lo), "=f"(hi) : "l"(v));
}

__device__ __forceinline__ void cp16(void* smem_dst, const void* gsrc, bool pred) {
    uint32_t sa = (uint32_t)__cvta_generic_to_shared(smem_dst);
    int sz = pred ? 16 : 0;
    asm volatile("cp.async.ca.shared.global [%0], [%1], 16, %2;"
                 :: "r"(sa), "l"(gsrc), "r"(sz));
}

__device__ __forceinline__ void cp4(void* smem_dst, const void* gsrc, bool pred) {
    uint32_t sa = (uint32_t)__cvta_generic_to_shared(smem_dst);
    int sz = pred ? 4 : 0;
    asm volatile("cp.async.ca.shared.global [%0], [%1], 4, %2;"
                 :: "r"(sa), "l"(gsrc), "r"(sz));
}

__device__ __forceinline__ void cp_commit() {
    asm volatile("cp.async.commit_group;");
}

__device__ __forceinline__ void cp_wait0() {
    asm volatile("cp.async.wait_group 0;");
}

// ---------------------------------------------------------------------------
// Prep: transpose + duplicate ALL weights in ONE launch.
// dst layout per weight: [CIN*K rows][2*CO], row r=(ci*K+tap), value duplicated
// at [2*co] and [2*co+1] so the conv kernel can LDS.64 straight into FFMA2.
// ---------------------------------------------------------------------------
// float offsets into g_wT (dup layout):
#define OFF_DS    0u          // CIN=64 K=1 : 64*256  = 16384
#define OFF_W10   16384u      // CIN=64 K=2 : 128*256 = 32768
#define OFF_W20   49152u      // CIN=128 K=2: 256*256 = 65536
#define OFF_L1(i) (114688u + (unsigned)(i) * 65536u)
#define OFF_L2(i) (376832u + (unsigned)(i) * 65536u)
#define WT_TOTAL  638976u

__global__ void prep_weights_kernel(const float* __restrict__ ds_w,
                                    const float* __restrict__ w1_0,
                                    const float* __restrict__ w2_0,
                                    const float* __restrict__ W1,
                                    const float* __restrict__ W2,
                                    float* __restrict__ dst) {
    const unsigned LWf = 128u * 128u * 2u;  // per-layer weight floats
    for (unsigned id = blockIdx.x * blockDim.x + threadIdx.x; id < WT_TOTAL;
         id += gridDim.x * blockDim.x) {
        const float* src;
        unsigned local, CIN, K;
        if (id < OFF_W10)          { src = ds_w;  local = id;            CIN = 64;  K = 1; }
        else if (id < OFF_W20)     { src = w1_0;  local = id - OFF_W10;  CIN = 64;  K = 2; }
        else if (id < OFF_L1(0))   { src = w2_0;  local = id - OFF_W20;  CIN = 128; K = 2; }
        else {
            unsigned seg = (id - OFF_L1(0)) / 65536u;   // 0..7
            local = (id - OFF_L1(0)) % 65536u;
            CIN = 128; K = 2;
            src = (seg < 4) ? (W1 + seg * LWf) : (W2 + (seg - 4) * LWf);
        }
        unsigned co  = (local >> 1) & 127u;
        unsigned r   = local >> 8;
        unsigned ci  = r / K;
        unsigned tap = r - ci * K;
        dst[id] = src[(co * CIN + ci) * K + tap];
    }
}

// ---------------------------------------------------------------------------
// Causal dilated conv (K=2) / 1x1 conv, CO=128, fused epilogues,
// double-buffered cp.async staging, duplicated-weight LDS.64 inner loop.
// MODE 0: out = elu(conv + bias)
// MODE 1: out = elu(elu(conv + bias) + res)
// MODE 2: out = elu(elu(conv + bias) + res) + skip
// MODE 3: out = conv + bias            (1x1 downsample, KSIZE=1, D=0)
// ---------------------------------------------------------------------------
template<int CIN, int KSIZE, int MODE, int D>
__global__ void __launch_bounds__(NTHREADS, 2)
conv_tb_kernel(const float* __restrict__ x,     // [B, CIN, S]
               const float* __restrict__ wD,    // duplicated [CIN*KSIZE][2*CO]
               const float* __restrict__ bias,  // [CO]
               const float* __restrict__ res,   // [B, CO, S] or null
               const float* __restrict__ skip,  // [B, CO, S] or null
               float* __restrict__ out)         // [B, CO, S]
{
    constexpr int S   = 4096;
    constexpr int W   = TT + D;
    constexpr int XR  = TT + DMAX;             // x row stride in smem (floats)
    constexpr int XSZ = CK * XR;               // per-buffer x floats
    constexpr int WSZ = CK * KSIZE * 2 * CO;   // per-buffer w floats (dup)
    constexpr int NCH = CIN / CK;
    constexpr bool ALIGNED = ((D & 3) == 0);   // 16B-aligned x rows

    extern __shared__ __align__(16) float smem[];
    float* sxb[2] = { smem, smem + XSZ };
    float* swb[2] = { smem + 2 * XSZ, smem + 2 * XSZ + WSZ };

    const int tid = threadIdx.x;
    const int tt  = tid & 15;   // time group:  t = t0 + 2*tt + 32*q + h
    const int tco = tid >> 4;   // co group:    co = tco + 16*c
    const int t0  = blockIdx.x * TT;
    const int b   = blockIdx.y;

    const float* xb = x + (size_t)b * CIN * S;

    unsigned long long acc[8][4];
    #pragma unroll
    for (int c = 0; c < 8; ++c)
        #pragma unroll
        for (int q = 0; q < 4; ++q) acc[c][q] = 0ull;

    // ---- async staging helper ----
    auto stage = [&](int k, int s) {
        int cc = k * CK;
        float* dx = sxb[s];
        if (ALIGNED) {
            constexpr int G = W / 4;  // 16B granules per row
            #pragma unroll 3
            for (int i = tid; i < CK * G; i += NTHREADS) {
                int ci = i / G;
                int j  = (i - ci * G) * 4;
                int t  = t0 - D + j;
                cp16(dx + ci * XR + j, xb + (size_t)(cc + ci) * S + t, t >= 0);
            }
        } else {
            #pragma unroll 3
            for (int i = tid; i < CK * W; i += NTHREADS) {
                int ci = i / W;
                int j  = i - ci * W;
                int t  = t0 - D + j;
                cp4(dx + ci * XR + j, xb + (size_t)(cc + ci) * S + t, t >= 0);
            }
        }
        const float* wsrc = wD + (size_t)cc * KSIZE * 2 * CO;
        float* dw = swb[s];
        #pragma unroll
        for (int i = tid; i < WSZ / 4; i += NTHREADS)
            cp16(dw + 4 * i, wsrc + 4 * i, true);
        cp_commit();
    };

    stage(0, 0);

    for (int k = 0; k < NCH; ++k) {
        int s = k & 1;
        cp_wait0();
        __syncthreads();
        if (k + 1 < NCH) stage(k + 1, s ^ 1);

        const float* sx = sxb[s];
        const float* sw = swb[s];

        #pragma unroll 2
        for (int ci = 0; ci < CK; ++ci) {
            const float* sxp = sx + ci * XR + 2 * tt;
            unsigned long long xd[4], xt[4];
            #pragma unroll
            for (int q = 0; q < 4; ++q) {
                if (KSIZE == 2)
                    xd[q] = *(const unsigned long long*)(sxp + 32 * q);       // x[t-D]
                if ((D & 1) == 0)
                    xt[q] = *(const unsigned long long*)(sxp + 32 * q + D);   // x[t]
                else
                    xt[q] = pack2(sxp[32 * q + D], sxp[32 * q + D + 1]);
            }
            #pragma unroll
            for (int c = 0; c < 8; ++c) {
                int co2 = 2 * (tco + 16 * c);
                if (KSIZE == 2) {
                    unsigned long long w0v =
                        *(const unsigned long long*)(sw + (2 * ci) * (2 * CO) + co2);
                    unsigned long long w1v =
                        *(const unsigned long long*)(sw + (2 * ci + 1) * (2 * CO) + co2);
                    #pragma unroll
                    for (int q = 0; q < 4; ++q) ffma2(acc[c][q], w0v, xd[q]);
                    #pragma unroll
                    for (int q = 0; q < 4; ++q) ffma2(acc[c][q], w1v, xt[q]);
                } else {
                    unsigned long long w1v =
                        *(const unsigned long long*)(sw + ci * (2 * CO) + co2);
                    #pragma unroll
                    for (int q = 0; q < 4; ++q) ffma2(acc[c][q], w1v, xt[q]);
                }
            }
        }
        __syncthreads();
    }

    // fused epilogue
    #pragma unroll
    for (int c = 0; c < 8; ++c) {
        int co = tco + 16 * c;
        float bv = __ldg(bias + co);
        size_t ob = ((size_t)b * CO + co) * S + t0 + 2 * tt;
        #pragma unroll
        for (int q = 0; q < 4; ++q) {
            float lo, hi;
            unpack2(acc[c][q], lo, hi);
            lo += bv; hi += bv;
            size_t o = ob + 32 * q;
            if (MODE == 0) {
                lo = eluf(lo); hi = eluf(hi);
            } else if (MODE == 1 || MODE == 2) {
                float2 r = *(const float2*)(res + o);
                lo = eluf(eluf(lo) + r.x);
                hi = eluf(eluf(hi) + r.y);
                if (MODE == 2) {
                    float2 s2 = *(const float2*)(skip + o);
                    lo += s2.x; hi += s2.y;
                }
            }
            // MODE 3: raw conv + bias
            *(float2*)(out + o) = make_float2(lo, hi);
        }
    }
}

// Scratch (device globals; no allocation in kernel_launch)
#define TENSOR_ELEMS ((size_t)16 * 128 * 4096)
__device__ float g_bufA[TENSOR_ELEMS];
__device__ float g_bufB[TENSOR_ELEMS];
__device__ float g_bufC[TENSOR_ELEMS];
__device__ float g_bufT[TENSOR_ELEMS];
__device__ float g_wT[WT_TOTAL];

extern "C" void kernel_launch(void* const* d_in, const int* in_sizes, int n_in,
                              void* d_out, int out_size) {
    const float* x    = (const float*)d_in[0];
    const float* w1_0 = (const float*)d_in[1];
    const float* b1_0 = (const float*)d_in[2];
    const float* w2_0 = (const float*)d_in[3];
    const float* b2_0 = (const float*)d_in[4];
    const float* ds_w = (const float*)d_in[5];
    const float* ds_b = (const float*)d_in[6];
    const float* W1   = (const float*)d_in[7];  // [4,128,128,2]
    const float* B1   = (const float*)d_in[8];  // [4,128]
    const float* W2   = (const float*)d_in[9];  // [4,128,128,2]
    const float* B2   = (const float*)d_in[10]; // [4,128]
    float* out = (float*)d_out;

    float *A, *Bf, *C, *T, *WTp;
    cudaGetSymbolAddress((void**)&A,   g_bufA);
    cudaGetSymbolAddress((void**)&Bf,  g_bufB);
    cudaGetSymbolAddress((void**)&C,   g_bufC);
    cudaGetSymbolAddress((void**)&T,   g_bufT);
    cudaGetSymbolAddress((void**)&WTp, g_wT);

    // ---- single prep launch ----
    prep_weights_kernel<<<256, 256>>>(ds_w, w1_0, w2_0, W1, W2, WTp);

    dim3 grid(4096 / TT, 16);

    // dynamic smem sizes (bytes)
    const int smemK2 = (2 * CK * (TT + DMAX) + 2 * CK * 2 * 2 * CO) * 4;  // 83968
    const int smemK1 = (2 * CK * (TT + DMAX) + 2 * CK * 1 * 2 * CO) * 4;  // 51200

    cudaFuncSetAttribute(conv_tb_kernel<64, 1, 3, 0>,   cudaFuncAttributeMaxDynamicSharedMemorySize, smemK1);
    cudaFuncSetAttribute(conv_tb_kernel<64, 2, 0, 1>,   cudaFuncAttributeMaxDynamicSharedMemorySize, smemK2);
    cudaFuncSetAttribute(conv_tb_kernel<128, 2, 1, 1>,  cudaFuncAttributeMaxDynamicSharedMemorySize, smemK2);
    cudaFuncSetAttribute(conv_tb_kernel<128, 2, 0, 2>,  cudaFuncAttributeMaxDynamicSharedMemorySize, smemK2);
    cudaFuncSetAttribute(conv_tb_kernel<128, 2, 1, 2>,  cudaFuncAttributeMaxDynamicSharedMemorySize, smemK2);
    cudaFuncSetAttribute(conv_tb_kernel<128, 2, 0, 4>,  cudaFuncAttributeMaxDynamicSharedMemorySize, smemK2);
    cudaFuncSetAttribute(conv_tb_kernel<128, 2, 1, 4>,  cudaFuncAttributeMaxDynamicSharedMemorySize, smemK2);
    cudaFuncSetAttribute(conv_tb_kernel<128, 2, 0, 8>,  cudaFuncAttributeMaxDynamicSharedMemorySize, smemK2);
    cudaFuncSetAttribute(conv_tb_kernel<128, 2, 1, 8>,  cudaFuncAttributeMaxDynamicSharedMemorySize, smemK2);
    cudaFuncSetAttribute(conv_tb_kernel<128, 2, 0, 16>, cudaFuncAttributeMaxDynamicSharedMemorySize, smemK2);
    cudaFuncSetAttribute(conv_tb_kernel<128, 2, 2, 16>, cudaFuncAttributeMaxDynamicSharedMemorySize, smemK2);

    // layer 0 (dilation 1, Cin=64, downsample residual)
    conv_tb_kernel<64, 1, 3, 0><<<grid, NTHREADS, smemK1>>>(x, WTp + OFF_DS, ds_b, nullptr, nullptr, C);  // C = ds(x)
    conv_tb_kernel<64, 2, 0, 1><<<grid, NTHREADS, smemK2>>>(x, WTp + OFF_W10, b1_0, nullptr, nullptr, T);
    conv_tb_kernel<128, 2, 1, 1><<<grid, NTHREADS, smemK2>>>(T, WTp + OFF_W20, b2_0, C, nullptr, A);      // A = x1

    // layer 1 (dilation 2)
    conv_tb_kernel<128, 2, 0, 2><<<grid, NTHREADS, smemK2>>>(A, WTp + OFF_L1(0), B1 + 0,  nullptr, nullptr, T);
    conv_tb_kernel<128, 2, 1, 2><<<grid, NTHREADS, smemK2>>>(T, WTp + OFF_L2(0), B2 + 0,  A, nullptr, Bf); // Bf = x2

    // layer 2 (dilation 4)
    conv_tb_kernel<128, 2, 0, 4><<<grid, NTHREADS, smemK2>>>(Bf, WTp + OFF_L1(1), B1 + 128, nullptr, nullptr, T);
    conv_tb_kernel<128, 2, 1, 4><<<grid, NTHREADS, smemK2>>>(T,  WTp + OFF_L2(1), B2 + 128, Bf, nullptr, C); // C = x3

    // layer 3 (dilation 8)
    conv_tb_kernel<128, 2, 0, 8><<<grid, NTHREADS, smemK2>>>(C, WTp + OFF_L1(2), B1 + 256, nullptr, nullptr, T);
    conv_tb_kernel<128, 2, 1, 8><<<grid, NTHREADS, smemK2>>>(T, WTp + OFF_L2(2), B2 + 256, C, nullptr, Bf);  // Bf = x4

    // layer 4 (dilation 16) + final skip add of x1 (A)
    conv_tb_kernel<128, 2, 0, 16><<<grid, NTHREADS, smemK2>>>(Bf, WTp + OFF_L1(3), B1 + 384, nullptr, nullptr, T);
    conv_tb_kernel<128, 2, 2, 16><<<grid, NTHREADS, smemK2>>>(T,  WTp + OFF_L2(3), B2 + 384, Bf, A, out);
}

// round 8
// speedup vs baseline: 1.9000x; 1.4874x over previous
#include <cuda_runtime.h>
#include <cuda_bf16.h>
#include <cstdint>

// ============================ helpers ============================

__device__ __forceinline__ void cp16(void* smem_dst, const void* gsrc, bool pred) {
    uint32_t sa = (uint32_t)__cvta_generic_to_shared(smem_dst);
    int sz = pred ? 16 : 0;
    asm volatile("cp.async.ca.shared.global [%0], [%1], 16, %2;"
                 :: "r"(sa), "l"(gsrc), "r"(sz));
}
__device__ __forceinline__ void cp_commit() { asm volatile("cp.async.commit_group;"); }
__device__ __forceinline__ void cp_wait0()  { asm volatile("cp.async.wait_group 0;"); }

__device__ __forceinline__ void ldmx4(uint32_t r[4], uint32_t addr) {
    asm volatile("ldmatrix.sync.aligned.m8n8.x4.shared.b16 {%0,%1,%2,%3}, [%4];"
                 : "=r"(r[0]), "=r"(r[1]), "=r"(r[2]), "=r"(r[3]) : "r"(addr));
}

__device__ __forceinline__ void mma16816(float c[4], const uint32_t a[4],
                                         uint32_t b0, uint32_t b1) {
    asm volatile(
        "mma.sync.aligned.m16n8k16.row.col.f32.bf16.bf16.f32 "
        "{%0,%1,%2,%3}, {%4,%5,%6,%7}, {%8,%9}, {%0,%1,%2,%3};"
        : "+f"(c[0]), "+f"(c[1]), "+f"(c[2]), "+f"(c[3])
        : "r"(a[0]), "r"(a[1]), "r"(a[2]), "r"(a[3]), "r"(b0), "r"(b1));
}

__device__ __forceinline__ float eluf(float v) {
    return v > 0.f ? v : expm1f(v);
}

// ============================ prep kernels ============================

// x [16][64][4096] fp32 -> act0 [16][4096][64] bf16 hi/lo (tiled transpose)
__global__ void prep_acts(const float* __restrict__ x,
                          __nv_bfloat16* __restrict__ h,
                          __nv_bfloat16* __restrict__ l) {
    __shared__ float tile[32][33];
    int tx = threadIdx.x & 31, ty = threadIdx.x >> 5;  // 32x8
    int t0 = blockIdx.x * 32, c0 = blockIdx.y * 32, b = blockIdx.z;
    #pragma unroll
    for (int k = 0; k < 4; ++k)
        tile[ty + 8 * k][tx] = x[((size_t)(b * 64 + c0 + ty + 8 * k)) * 4096 + t0 + tx];
    __syncthreads();
    #pragma unroll
    for (int k = 0; k < 4; ++k) {
        float v = tile[tx][ty + 8 * k];
        size_t o = ((size_t)(b * 4096 + t0 + ty + 8 * k)) * 64 + c0 + tx;
        __nv_bfloat16 hh = __float2bfloat16(v);
        h[o] = hh;
        l[o] = __float2bfloat16(v - __bfloat162float(hh));
    }
}

// Weight operands: per conv [co][Ktot] bf16.
// K2 slices s: {hi t0, hi t1, lo t0, lo t1, hi t0, hi t1}; K1: {hi, hi, lo}
#define WP_DS    0u
#define WP_C10   24576u
#define WP_C20   73728u
#define WP_L(s)  (73728u + (unsigned)(s) * 98304u)
#define WP_TOTAL 958464u

__global__ void prep_weights(const float* __restrict__ ds_w,
                             const float* __restrict__ w1_0,
                             const float* __restrict__ w2_0,
                             const float* __restrict__ W1,
                             const float* __restrict__ W2,
                             __nv_bfloat16* __restrict__ dst) {
    const unsigned LWf = 128u * 128u * 2u;
    for (unsigned id = blockIdx.x * blockDim.x + threadIdx.x; id < WP_TOTAL;
         id += gridDim.x * blockDim.x) {
        float w;
        unsigned s;
        bool isK1 = false;
        if (id < WP_C10) {                    // ds: CIN=64 K=1, Ktot=192
            unsigned local = id;
            unsigned co = local / 192, rem = local % 192;
            s = rem / 64;
            unsigned ci = rem % 64;
            w = ds_w[co * 64 + ci];
            isK1 = true;
        } else if (id < WP_C20) {             // c1_0: CIN=64 K=2, Ktot=384
            unsigned local = id - WP_C10;
            unsigned co = local / 384, rem = local % 384;
            s = rem / 64;
            unsigned ci = rem % 64, tap = s & 1;
            w = w1_0[(co * 64 + ci) * 2 + tap];
        } else {                              // CIN=128 K=2, Ktot=768
            unsigned local = id - WP_C20;
            unsigned seg = local / 98304u;    // 0..8
            unsigned rem = local % 98304u;
            unsigned co = rem / 768, r = rem % 768;
            s = r / 128;
            unsigned ci = r % 128, tap = s & 1;
            const float* src = (seg == 0) ? w2_0
                             : ((seg & 1) ? (W1 + ((seg - 1) / 2) * LWf)
                                          : (W2 + (seg / 2 - 1) * LWf));
            w = src[(co * 128 + ci) * 2 + tap];
        }
        bool lo = isK1 ? (s == 2) : (s >= 2 && s < 4);
        __nv_bfloat16 hh = __float2bfloat16(w);
        __nv_bfloat16 v = lo ? __float2bfloat16(w - __bfloat162float(hh)) : hh;
        dst[id] = v;
    }
}

// ============================ conv kernel (mma.sync bf16) ============================
// D[co=128, t=128] per CTA. K_eff = 3*KSIZE*CIN (bf16 hi/lo 3-term split).
// A = weights [co][k] row-major smem (ldmatrix non-trans).
// B = acts [t][ci] row-major smem == col-major B (ldmatrix non-trans).
// MODE 0: elu(conv+b) -> hi/lo bf16 [b][t][co]
// MODE 1: elu(elu(conv+b)+res) -> hi/lo
// MODE 2: final: elu(elu(conv+b)+res)+skip -> fp32 [b][co][t]
// MODE 3: conv+b -> fp32 [b][t][co] (downsample)
template<int CIN, int KSIZE, int MODE, int D, bool RESF32>
__global__ void __launch_bounds__(256, 1)
conv_tc(const __nv_bfloat16* __restrict__ in_hi,
        const __nv_bfloat16* __restrict__ in_lo,
        const __nv_bfloat16* __restrict__ wp,      // [128][Ktot] bf16
        const float* __restrict__ bias,
        const void* __restrict__ res_h,            // float* if RESF32 else bf16*
        const __nv_bfloat16* __restrict__ res_l,
        const __nv_bfloat16* __restrict__ skip_h,
        const __nv_bfloat16* __restrict__ skip_l,
        void* __restrict__ out_h,                  // bf16* or float* per MODE
        __nv_bfloat16* __restrict__ out_l)
{
    constexpr int NSEG  = 3 * KSIZE;
    constexpr int KTOT  = NSEG * CIN;
    constexpr int PAD   = (CIN == 128) ? 136 : 72;   // bf16 row stride (A and B)
    constexpr int RB    = PAD * 2;                   // row bytes
    constexpr int BROWS = 128 + D;
    constexpr int BT    = BROWS * RB;                // one B buffer bytes
    constexpr int AT    = 128 * RB;                  // one A buffer bytes
    constexpr int GPB   = CIN / 8;                   // 16B granules per row
    constexpr int KS    = CIN / 16;                  // k16 steps per segment

    extern __shared__ __align__(16) char smem[];
    char* smBhi = smem;
    char* smBlo = smem + BT;
    char* smA[2] = { smem + 2 * BT, smem + 2 * BT + AT };
    float* tr = (float*)smem;                        // reused post-compute
    __shared__ float sbias[128];

    const int tid  = threadIdx.x;
    const int lane = tid & 31;
    const int w    = tid >> 5;
    const int t0   = blockIdx.x * 128;
    const int b    = blockIdx.y;
    const int m0w  = (w & 1) * 64;
    const int n0w  = (w >> 1) * 32;

    if (tid < 128) sbias[tid] = bias[tid];

    // ---- stage B (both hi and lo), rows t0-D .. t0+127 ----
    for (int i = tid; i < BROWS * GPB; i += 256) {
        int r = i / GPB, gi = i - r * GPB;
        int t = t0 - D + r;
        const size_t gofs = ((size_t)(b * 4096 + t)) * CIN + gi * 8;
        cp16(smBhi + r * RB + gi * 16, in_hi + gofs, t >= 0);
        cp16(smBlo + r * RB + gi * 16, in_lo + gofs, t >= 0);
    }
    // ---- stage A segment 0 ----
    for (int i = tid; i < 128 * GPB; i += 256) {
        int r = i / GPB, gi = i - r * GPB;
        cp16(smA[0] + r * RB + gi * 16, wp + (size_t)r * KTOT + gi * 8, true);
    }
    cp_commit();

    // ---- ldmatrix lane base offsets ----
    const uint32_t aRow  = m0w + (lane & 15);
    const uint32_t aColB = ((lane >> 4) * 8) * 2;
    const uint32_t bRow  = n0w + (lane & 7) + ((lane >> 4) << 3);
    const uint32_t bColB = (((lane >> 3) & 1) * 8) * 2;

    float acc[4][4][4];
    #pragma unroll
    for (int mt = 0; mt < 4; ++mt)
        #pragma unroll
        for (int nt = 0; nt < 4; ++nt)
            #pragma unroll
            for (int j = 0; j < 4; ++j) acc[mt][nt][j] = 0.f;

    #pragma unroll 1
    for (int s = 0; s < NSEG; ++s) {
        cp_wait0();
        __syncthreads();
        if (s + 1 < NSEG) {
            char* dA = smA[(s + 1) & 1];
            const __nv_bfloat16* wsrc = wp + (size_t)(s + 1) * CIN;
            for (int i = tid; i < 128 * GPB; i += 256) {
                int r = i / GPB, gi = i - r * GPB;
                cp16(dA + r * RB + gi * 16, wsrc + (size_t)r * KTOT + gi * 8, true);
            }
            cp_commit();
        }

        // segment -> (x buffer, row shift)
        const bool xlo  = (KSIZE == 2) ? (s >= 4) : (s == 1);
        const int  rAdd = (KSIZE == 2) ? ((s & 1) ? D : 0) : 0;

        const uint32_t aBase = (uint32_t)__cvta_generic_to_shared(smA[s & 1]) +
                               aRow * RB + aColB;
        const uint32_t bBase = (uint32_t)__cvta_generic_to_shared(xlo ? smBlo : smBhi) +
                               (bRow + rAdd) * RB + bColB;

        #pragma unroll
        for (int kk = 0; kk < KS; ++kk) {
            const uint32_t ko = kk * 32;   // 16 bf16
            uint32_t a[4][4];
            #pragma unroll
            for (int mt = 0; mt < 4; ++mt)
                ldmx4(a[mt], aBase + mt * 16 * RB + ko);
            uint32_t b0[4], b1[4];
            ldmx4(b0, bBase + ko);                 // n tiles 0,1
            ldmx4(b1, bBase + 16 * RB + ko);       // n tiles 2,3
            #pragma unroll
            for (int mt = 0; mt < 4; ++mt) {
                mma16816(acc[mt][0], a[mt], b0[0], b0[1]);
                mma16816(acc[mt][1], a[mt], b0[2], b0[3]);
                mma16816(acc[mt][2], a[mt], b1[0], b1[1]);
                mma16816(acc[mt][3], a[mt], b1[2], b1[3]);
            }
        }
    }

    __syncthreads();   // compute done; smem reusable

    // ---- phase A: accum -> smem [t][co] (+bias) ----
    {
        int g = lane >> 2, tig = lane & 3;
        #pragma unroll
        for (int mt = 0; mt < 4; ++mt)
            #pragma unroll
            for (int nt = 0; nt < 4; ++nt)
                #pragma unroll
                for (int j = 0; j < 4; ++j) {
                    int co = m0w + mt * 16 + g + ((j & 2) ? 8 : 0);
                    int tl = n0w + nt * 8 + tig * 2 + (j & 1);
                    tr[tl * 129 + co] = acc[mt][nt][j] + sbias[co];
                }
    }
    __syncthreads();

    // ---- phase B: epilogue, [t][co] order (coalesced) ----
    {
        int co = tid & 127;
        int r0 = tid >> 7;
        #pragma unroll 4
        for (int i = 0; i < 64; ++i) {
            int r = r0 + 2 * i;
            int t = t0 + r;
            size_t gidx = ((size_t)(b * 4096 + t)) * 128 + co;
            float v = tr[r * 129 + co];
            float y;
            if (MODE == 0) {
                y = eluf(v);
            } else if (MODE == 3) {
                y = v;
            } else {
                float rv;
                if (RESF32)
                    rv = ((const float*)res_h)[gidx];
                else
                    rv = __bfloat162float(((const __nv_bfloat16*)res_h)[gidx]) +
                         __bfloat162float(res_l[gidx]);
                y = eluf(eluf(v) + rv);
                if (MODE == 2)
                    y += __bfloat162float(skip_h[gidx]) +
                         __bfloat162float(skip_l[gidx]);
            }
            if (MODE == 3) {
                ((float*)out_h)[gidx] = y;
            } else if (MODE == 2) {
                tr[r * 129 + co] = y;    // own slot; transposed write next
            } else {
                __nv_bfloat16 hh = __float2bfloat16(y);
                ((__nv_bfloat16*)out_h)[gidx] = hh;
                out_l[gidx] = __float2bfloat16(y - __bfloat162float(hh));
            }
        }
    }

    if (MODE == 2) {
        __syncthreads();
        float* outp = (float*)out_h;
        for (int co = w; co < 128; co += 8) {
            #pragma unroll
            for (int m = 0; m < 4; ++m) {
                int r = lane + 32 * m;
                outp[((size_t)(b * 128 + co)) * 4096 + t0 + r] = tr[r * 129 + co];
            }
        }
    }
}

// ============================ scratch ============================

#define AE64  ((size_t)16 * 4096 * 64)
#define AE128 ((size_t)16 * 4096 * 128)
__device__ __nv_bfloat16 g_a0h[AE64], g_a0l[AE64];
__device__ __nv_bfloat16 g_Th[AE128], g_Tl[AE128];
__device__ __nv_bfloat16 g_Ah[AE128], g_Al[AE128];
__device__ __nv_bfloat16 g_Bh[AE128], g_Bl[AE128];
__device__ __nv_bfloat16 g_Ch[AE128], g_Cl[AE128];
__device__ float         g_ds[AE128];
__device__ __nv_bfloat16 g_wp[WP_TOTAL];

// host-side smem size mirror
static int smem_for(int CIN, int D) {
    int pad = (CIN == 128) ? 136 : 72;
    int rb = pad * 2;
    int stage = (128 + D) * rb * 2 + 2 * 128 * rb;
    int tr = 128 * 129 * 4;
    return stage > tr ? stage : tr;
}

// ============================ launcher ============================

extern "C" void kernel_launch(void* const* d_in, const int* in_sizes, int n_in,
                              void* d_out, int out_size) {
    const float* x    = (const float*)d_in[0];
    const float* w1_0 = (const float*)d_in[1];
    const float* b1_0 = (const float*)d_in[2];
    const float* w2_0 = (const float*)d_in[3];
    const float* b2_0 = (const float*)d_in[4];
    const float* ds_w = (const float*)d_in[5];
    const float* ds_b = (const float*)d_in[6];
    const float* W1   = (const float*)d_in[7];
    const float* B1   = (const float*)d_in[8];
    const float* W2   = (const float*)d_in[9];
    const float* B2   = (const float*)d_in[10];
    float* out = (float*)d_out;

    __nv_bfloat16 *a0h, *a0l, *Th, *Tl, *Ah, *Al, *Bh, *Bl, *Ch, *Cl, *wp;
    float *dsO;
    cudaGetSymbolAddress((void**)&a0h, g_a0h); cudaGetSymbolAddress((void**)&a0l, g_a0l);
    cudaGetSymbolAddress((void**)&Th, g_Th);   cudaGetSymbolAddress((void**)&Tl, g_Tl);
    cudaGetSymbolAddress((void**)&Ah, g_Ah);   cudaGetSymbolAddress((void**)&Al, g_Al);
    cudaGetSymbolAddress((void**)&Bh, g_Bh);   cudaGetSymbolAddress((void**)&Bl, g_Bl);
    cudaGetSymbolAddress((void**)&Ch, g_Ch);   cudaGetSymbolAddress((void**)&Cl, g_Cl);
    cudaGetSymbolAddress((void**)&dsO, g_ds);  cudaGetSymbolAddress((void**)&wp, g_wp);

    prep_weights<<<512, 256>>>(ds_w, w1_0, w2_0, W1, W2, wp);
    prep_acts<<<dim3(128, 2, 16), 256>>>(x, a0h, a0l);

    dim3 grid(32, 16);

    #define SETSM(CIN, KS, MODE, D, RF) cudaFuncSetAttribute( \
        (conv_tc<CIN, KS, MODE, D, RF>), \
        cudaFuncAttributeMaxDynamicSharedMemorySize, smem_for(CIN, D))
    SETSM(64, 1, 3, 0, false);
    SETSM(64, 2, 0, 1, false);
    SETSM(128, 2, 1, 1, true);
    SETSM(128, 2, 0, 2, false);
    SETSM(128, 2, 1, 2, false);
    SETSM(128, 2, 0, 4, false);
    SETSM(128, 2, 1, 4, false);
    SETSM(128, 2, 0, 8, false);
    SETSM(128, 2, 1, 8, false);
    SETSM(128, 2, 0, 16, false);
    SETSM(128, 2, 2, 16, false);

    // layer 0
    conv_tc<64, 1, 3, 0, false><<<grid, 256, smem_for(64, 0)>>>(
        a0h, a0l, wp + WP_DS, ds_b, nullptr, nullptr, nullptr, nullptr, dsO, nullptr);
    conv_tc<64, 2, 0, 1, false><<<grid, 256, smem_for(64, 1)>>>(
        a0h, a0l, wp + WP_C10, b1_0, nullptr, nullptr, nullptr, nullptr, Th, Tl);
    conv_tc<128, 2, 1, 1, true><<<grid, 256, smem_for(128, 1)>>>(
        Th, Tl, wp + WP_C20, b2_0, dsO, nullptr, nullptr, nullptr, Ah, Al);   // A = x1
    // layer 1 (d=2)
    conv_tc<128, 2, 0, 2, false><<<grid, 256, smem_for(128, 2)>>>(
        Ah, Al, wp + WP_L(1), B1 + 0, nullptr, nullptr, nullptr, nullptr, Th, Tl);
    conv_tc<128, 2, 1, 2, false><<<grid, 256, smem_for(128, 2)>>>(
        Th, Tl, wp + WP_L(2), B2 + 0, Ah, Al, nullptr, nullptr, Bh, Bl);      // B = x2
    // layer 2 (d=4)
    conv_tc<128, 2, 0, 4, false><<<grid, 256, smem_for(128, 4)>>>(
        Bh, Bl, wp + WP_L(3), B1 + 128, nullptr, nullptr, nullptr, nullptr, Th, Tl);
    conv_tc<128, 2, 1, 4, false><<<grid, 256, smem_for(128, 4)>>>(
        Th, Tl, wp + WP_L(4), B2 + 128, Bh, Bl, nullptr, nullptr, Ch, Cl);    // C = x3
    // layer 3 (d=8)
    conv_tc<128, 2, 0, 8, false><<<grid, 256, smem_for(128, 8)>>>(
        Ch, Cl, wp + WP_L(5), B1 + 256, nullptr, nullptr, nullptr, nullptr, Th, Tl);
    conv_tc<128, 2, 1, 8, false><<<grid, 256, smem_for(128, 8)>>>(
        Th, Tl, wp + WP_L(6), B2 + 256, Ch, Cl, nullptr, nullptr, Bh, Bl);    // B = x4
    // layer 4 (d=16) + final skip (x1 = A)
    conv_tc<128, 2, 0, 16, false><<<grid, 256, smem_for(128, 16)>>>(
        Bh, Bl, wp + WP_L(7), B1 + 384, nullptr, nullptr, nullptr, nullptr, Th, Tl);
    conv_tc<128, 2, 2, 16, false><<<grid, 256, smem_for(128, 16)>>>(
        Th, Tl, wp + WP_L(8), B2 + 384, Bh, Bl, Ah, Al, out, nullptr);
}